// round 7
// baseline (speedup 1.0000x reference)
#include <cuda_runtime.h>
#include <cuda_bf16.h>
#include <cstdint>

#define BATCH   8
#define SEQ     4096
#define D_HID   1024
#define N_HEADS 16
#define D_HEAD  64
#define M_TOT   (BATCH * SEQ)     // 32768
#define N_TOT   (3 * D_HID)       // 3072
#define K_TOT   (D_HID)           // 1024

// Scratch (allocation-free rule: __device__ globals)
__device__ __nv_bfloat16 g_qkvh[(size_t)M_TOT * N_TOT];   // qkv hi plane
__device__ __nv_bfloat16 g_qkvl[(size_t)M_TOT * N_TOT];   // qkv lo plane
__device__ float g_part[(size_t)8 * 128 * 4096];
__device__ __nv_bfloat16 g_ath[(size_t)128 * 4096];       // attn^T [bh][e][d] hi
__device__ __nv_bfloat16 g_atl[(size_t)128 * 4096];       // attn^T lo
__device__ __nv_bfloat16 g_xh[(size_t)M_TOT * K_TOT];
__device__ __nv_bfloat16 g_xl[(size_t)M_TOT * K_TOT];
__device__ __nv_bfloat16 g_wth[(size_t)N_TOT * K_TOT];
__device__ __nv_bfloat16 g_wtl[(size_t)N_TOT * K_TOT];

// ---------------------------------------------------------------------------
// helpers
// ---------------------------------------------------------------------------
__device__ __forceinline__ uint32_t smem_u32(const void* p) {
    uint32_t a;
    asm("{ .reg .u64 t; cvta.to.shared.u64 t, %1; cvt.u32.u64 %0, t; }" : "=r"(a) : "l"(p));
    return a;
}
__device__ __forceinline__ void cp16(uint32_t smem_dst, const void* gsrc) {
    asm volatile("cp.async.cg.shared.global [%0], [%1], 16;" :: "r"(smem_dst), "l"(gsrc));
}
__device__ __forceinline__ void cp_commit() {
    asm volatile("cp.async.commit_group;" ::: "memory");
}
__device__ __forceinline__ void ldsm4(uint32_t* r, uint32_t addr) {
    asm volatile("ldmatrix.sync.aligned.m8n8.x4.shared.b16 {%0,%1,%2,%3}, [%4];"
                 : "=r"(r[0]), "=r"(r[1]), "=r"(r[2]), "=r"(r[3]) : "r"(addr));
}
__device__ __forceinline__ void ldsm4t(uint32_t* r, uint32_t addr) {
    asm volatile("ldmatrix.sync.aligned.m8n8.x4.trans.shared.b16 {%0,%1,%2,%3}, [%4];"
                 : "=r"(r[0]), "=r"(r[1]), "=r"(r[2]), "=r"(r[3]) : "r"(addr));
}
__device__ __forceinline__ void mma16816(float* c, const uint32_t* a, const uint32_t* b) {
    asm volatile("mma.sync.aligned.m16n8k16.row.col.f32.bf16.bf16.f32 "
                 "{%0,%1,%2,%3}, {%4,%5,%6,%7}, {%8,%9}, {%0,%1,%2,%3};"
                 : "+f"(c[0]), "+f"(c[1]), "+f"(c[2]), "+f"(c[3])
                 : "r"(a[0]), "r"(a[1]), "r"(a[2]), "r"(a[3]), "r"(b[0]), "r"(b[1]));
}
__device__ __forceinline__ uint32_t pack_bf16(float x, float y) {
    __nv_bfloat162 t = __floats2bfloat162_rn(x, y);
    return *reinterpret_cast<uint32_t*>(&t);
}

// ---------------------------------------------------------------------------
// Conversion kernels (fp32 -> bf16 hi/lo split)
// ---------------------------------------------------------------------------
__global__ __launch_bounds__(256) void convert_x_kernel(const float* __restrict__ x)
{
    size_t i = ((size_t)blockIdx.x * 256 + threadIdx.x) * 8;
    float4 a = *(const float4*)(x + i);
    float4 b = *(const float4*)(x + i + 4);
    float v[8] = {a.x, a.y, a.z, a.w, b.x, b.y, b.z, b.w};
    __nv_bfloat16 hi[8], lo[8];
#pragma unroll
    for (int j = 0; j < 8; j++) {
        hi[j] = __float2bfloat16(v[j]);
        lo[j] = __float2bfloat16(v[j] - __bfloat162float(hi[j]));
    }
    *(uint4*)(g_xh + i) = *(uint4*)hi;
    *(uint4*)(g_xl + i) = *(uint4*)lo;
}

__global__ __launch_bounds__(256) void convert_w_kernel(const float* __restrict__ W)
{
    __shared__ float t[32][33];
    int x0 = blockIdx.x * 32;
    int y0 = blockIdx.y * 32;
    int tx = threadIdx.x, ty = threadIdx.y;
#pragma unroll
    for (int j = 0; j < 4; j++)
        t[ty + j * 8][tx] = W[(size_t)(y0 + ty + j * 8) * N_TOT + x0 + tx];
    __syncthreads();
#pragma unroll
    for (int j = 0; j < 4; j++) {
        int n = x0 + ty + j * 8;
        int k = y0 + tx;
        float v = t[tx][ty + j * 8];
        __nv_bfloat16 hi = __float2bfloat16(v);
        __nv_bfloat16 lo = __float2bfloat16(v - __bfloat162float(hi));
        g_wth[(size_t)n * K_TOT + k] = hi;
        g_wtl[(size_t)n * K_TOT + k] = lo;
    }
}

// ---------------------------------------------------------------------------
// K1: qkv = x @ W + b, mma.sync bf16 3-term split.
// Block 256x192, 384 threads (12 warps, 4x3 of 64x64 tiles), BK=64, 3 stages.
// ---------------------------------------------------------------------------
#define BM 256
#define BN 192
#define BK 64
#define NCHUNK 48
#define STAGE_BYTES 57344              // A 32KB + B 24KB
#define A_OFF(s) ((s) * STAGE_BYTES)
#define B_OFF(s) ((s) * STAGE_BYTES + 32768)
#define GEMM_SMEM (3 * STAGE_BYTES)    // 168 KB

__device__ __forceinline__ void load_chunk(uint32_t sb, int tid, int by, int bx, int c, int s)
{
    int seg  = c >> 4;
    int koff = (c & 15) * BK;
    const __nv_bfloat16* A = (seg == 2 ? g_xl : g_xh) + (size_t)(by * BM) * K_TOT + koff;
    const __nv_bfloat16* B = (seg == 1 ? g_wtl : g_wth) + (size_t)(bx * BN) * K_TOT + koff;
    uint32_t ab = sb + A_OFF(s), bb = sb + B_OFF(s);
#pragma unroll
    for (int i = 0; i < 6; i++) {            // A: 2048 slots
        int slot = i * 384 + tid;
        if (slot < 2048) {
            int r   = slot >> 3;
            int c16 = slot & 7;
            uint32_t off = (uint32_t)(r * 128 + ((c16 ^ (r & 7)) * 16));
            cp16(ab + off, A + (size_t)r * K_TOT + c16 * 8);
        }
    }
#pragma unroll
    for (int i = 0; i < 4; i++) {            // B: 1536 slots
        int slot = i * 384 + tid;
        int r   = slot >> 3;
        int c16 = slot & 7;
        uint32_t off = (uint32_t)(r * 128 + ((c16 ^ (r & 7)) * 16));
        cp16(bb + off, B + (size_t)r * K_TOT + c16 * 8);
    }
}

__global__ __launch_bounds__(384, 1) void qkv_mma_kernel(const float* __restrict__ bias)
{
    extern __shared__ __align__(128) uint8_t smem[];
    uint32_t sb = smem_u32(smem);
    const int tid  = threadIdx.x;
    const int wid  = tid >> 5;
    const int lane = tid & 31;
    const int bx = blockIdx.x;    // N tile 0..15
    const int by = blockIdx.y;    // M tile 0..127
    const int wm = wid >> 2;      // 0..2? no: 12 warps -> wm = wid / 3
    // 12 warps arranged 4 (M) x 3 (N)
    const int wmm = wid / 3;      // 0..3  (64 M each)
    const int wnn = wid % 3;      // 0..2  (64 N each)
    (void)wm;

    float acc[4][8][4];
#pragma unroll
    for (int mt = 0; mt < 4; mt++)
#pragma unroll
        for (int nt = 0; nt < 8; nt++)
#pragma unroll
            for (int j = 0; j < 4; j++) acc[mt][nt][j] = 0.f;

    load_chunk(sb, tid, by, bx, 0, 0); cp_commit();
    load_chunk(sb, tid, by, bx, 1, 1); cp_commit();

    const int a_r = wmm * 64 + (lane & 15);
    const int a_h = lane >> 4;
    const int b_r = wnn * 64 + ((lane >> 4) << 3) + (lane & 7);
    const int b_h = (lane >> 3) & 1;

    for (int ch = 0; ch < NCHUNK; ch++) {
        const int s = ch % 3;
        asm volatile("cp.async.wait_group 1;" ::: "memory");
        __syncthreads();
        if (ch + 2 < NCHUNK) load_chunk(sb, tid, by, bx, ch + 2, (ch + 2) % 3);
        cp_commit();

        const uint32_t abase = sb + A_OFF(s);
        const uint32_t bbase = sb + B_OFF(s);
#pragma unroll
        for (int ks = 0; ks < 4; ks++) {
            uint32_t a[4][4];
#pragma unroll
            for (int mt = 0; mt < 4; mt++) {
                int r   = a_r + mt * 16;
                int c16 = ks * 2 + a_h;
                ldsm4(a[mt], abase + r * 128 + ((c16 ^ (r & 7)) * 16));
            }
            // one B x4 fragment live at a time (register pressure)
#pragma unroll
            for (int np = 0; np < 4; np++) {
                int r   = b_r + np * 16;
                int c16 = ks * 2 + b_h;
                uint32_t q[4];
                ldsm4(q, bbase + r * 128 + ((c16 ^ (r & 7)) * 16));
#pragma unroll
                for (int mt = 0; mt < 4; mt++) {
                    mma16816(acc[mt][np * 2 + 0], a[mt], q + 0);
                    mma16816(acc[mt][np * 2 + 1], a[mt], q + 2);
                }
            }
        }
    }
    asm volatile("cp.async.wait_group 0;" ::: "memory");

    // Epilogue: +bias, split fp32 -> bf16 hi/lo planes
    const int ncol0 = bx * BN + wnn * 64 + (lane & 3) * 2;
    float b0[8], b1[8];
#pragma unroll
    for (int nt = 0; nt < 8; nt++) {
        b0[nt] = __ldg(bias + ncol0 + nt * 8);
        b1[nt] = __ldg(bias + ncol0 + nt * 8 + 1);
    }
#pragma unroll
    for (int mt = 0; mt < 4; mt++)
#pragma unroll
        for (int half = 0; half < 2; half++) {
            int m = by * BM + wmm * 64 + mt * 16 + (lane >> 2) + half * 8;
            size_t base = (size_t)m * N_TOT + ncol0;
#pragma unroll
            for (int nt = 0; nt < 8; nt++) {
                float vx = acc[mt][nt][half * 2 + 0] + b0[nt];
                float vy = acc[mt][nt][half * 2 + 1] + b1[nt];
                __nv_bfloat16 hx = __float2bfloat16(vx);
                __nv_bfloat16 hy = __float2bfloat16(vy);
                *(uint32_t*)(g_qkvh + base + nt * 8) = pack_bf16(vx, vy);
                *(uint32_t*)(g_qkvl + base + nt * 8) =
                    pack_bf16(vx - __bfloat162float(hx), vy - __bfloat162float(hy));
            }
        }
}

// ---------------------------------------------------------------------------
// K2a: partial S over a 512-n chunk, tensor cores, bf16 planes via ldmatrix.trans.
// grid (8, 128). 256 threads. Subtile 64n, 2-stage cp.async (64KB smem).
// ---------------------------------------------------------------------------
#define K2_SMEM 65536

__device__ __forceinline__ void k2_load_sub(uint32_t sb, int tid,
                                            const __nv_bfloat16* qh, const __nv_bfloat16* ql,
                                            const __nv_bfloat16* kh, const __nv_bfloat16* kl,
                                            int n0, int stg)
{
    const __nv_bfloat16* src[4] = {qh, ql, kh, kl};
    uint32_t base = sb + stg * 32768;
#pragma unroll
    for (int p = 0; p < 4; p++) {
#pragma unroll
        for (int i = 0; i < 2; i++) {
            int slot = i * 256 + tid;
            int r   = slot >> 3;
            int c16 = slot & 7;
            uint32_t off = (uint32_t)(r * 128 + ((c16 ^ (r & 7)) << 4));
            cp16(base + p * 8192 + off, src[p] + (size_t)(n0 + r) * N_TOT + c16 * 8);
        }
    }
}

__global__ __launch_bounds__(256) void attn_part_kernel()
{
    extern __shared__ __align__(128) uint8_t smem[];
    uint32_t sb = smem_u32(smem);
    const int tid   = threadIdx.x;
    const int wid   = tid >> 5;
    const int lane  = tid & 31;
    const int chunk = blockIdx.x;
    const int bh    = blockIdx.y;
    const int b     = bh >> 4, h = bh & 15;

    const __nv_bfloat16* qh = g_qkvh + (size_t)b * SEQ * N_TOT + h * 64;
    const __nv_bfloat16* ql = g_qkvl + (size_t)b * SEQ * N_TOT + h * 64;
    const __nv_bfloat16* kh = qh + D_HID;
    const __nv_bfloat16* kl = ql + D_HID;

    const int wm = wid >> 2;
    const int wn = wid & 3;

    const int an = ((lane >> 4) & 1) * 8 + (lane & 7);
    const int ac = ((lane >> 3) & 1);
    const int bn = ((lane >> 3) & 1) * 8 + (lane & 7);
    const int bc = wn * 2 + (lane >> 4);

    float acc[2][2][4];
#pragma unroll
    for (int mt = 0; mt < 2; mt++)
#pragma unroll
        for (int nt = 0; nt < 2; nt++)
#pragma unroll
            for (int j = 0; j < 4; j++) acc[mt][nt][j] = 0.f;

    const int nbase = chunk * 512;
    k2_load_sub(sb, tid, qh, ql, kh, kl, nbase, 0);
    cp_commit();

    for (int t = 0; t < 8; t++) {
        __syncthreads();
        if (t + 1 < 8) k2_load_sub(sb, tid, qh, ql, kh, kl, nbase + (t + 1) * 64, (t + 1) & 1);
        cp_commit();
        asm volatile("cp.async.wait_group 1;" ::: "memory");
        __syncthreads();

        uint32_t stg = sb + (t & 1) * 32768;
#pragma unroll
        for (int ks = 0; ks < 4; ks++) {
            uint32_t aqh[2][4], aql[2][4];
#pragma unroll
            for (int mt = 0; mt < 2; mt++) {
                int n   = ks * 16 + an;
                int c16 = wm * 4 + mt * 2 + ac;
                uint32_t off = (uint32_t)(n * 128 + ((c16 ^ (n & 7)) << 4));
                ldsm4t(aqh[mt], stg + off);
                ldsm4t(aql[mt], stg + 8192 + off);
            }
            uint32_t bkh[2][2], bkl[2][2];
            {
                int n   = ks * 16 + bn;
                uint32_t off = (uint32_t)(n * 128 + ((bc ^ (n & 7)) << 4));
                uint32_t q[4];
                ldsm4t(q, stg + 16384 + off);
                bkh[0][0] = q[0]; bkh[0][1] = q[1]; bkh[1][0] = q[2]; bkh[1][1] = q[3];
                ldsm4t(q, stg + 24576 + off);
                bkl[0][0] = q[0]; bkl[0][1] = q[1]; bkl[1][0] = q[2]; bkl[1][1] = q[3];
            }
#pragma unroll
            for (int mt = 0; mt < 2; mt++)
#pragma unroll
                for (int nt = 0; nt < 2; nt++) {
                    mma16816(acc[mt][nt], aqh[mt], bkh[nt]);
                    mma16816(acc[mt][nt], aqh[mt], bkl[nt]);
                    mma16816(acc[mt][nt], aql[mt], bkh[nt]);
                }
        }
    }

    float* pg = g_part + ((size_t)chunk * 128 + bh) * 4096;
#pragma unroll
    for (int mt = 0; mt < 2; mt++)
#pragma unroll
        for (int nt = 0; nt < 2; nt++)
#pragma unroll
            for (int half = 0; half < 2; half++) {
                int d = wm * 32 + mt * 16 + (lane >> 2) + half * 8;
                int e = wn * 16 + nt * 8 + (lane & 3) * 2;
                float2 v;
                v.x = acc[mt][nt][half * 2 + 0];
                v.y = acc[mt][nt][half * 2 + 1];
                *(float2*)(pg + d * 64 + e) = v;
            }
}

// ---------------------------------------------------------------------------
// K2b: reduce 8 partials, scale, softmax over e; emit attn^T bf16 hi/lo.
// ---------------------------------------------------------------------------
__global__ __launch_bounds__(256) void attn_softmax_kernel()
{
    __shared__ float S[64 * 68 + 128];
    float* mrow = S + 64 * 68;
    float* irow = mrow + 64;

    const int tid = threadIdx.x;
    const int bh  = blockIdx.x;

#pragma unroll
    for (int i = 0; i < 16; i++) {
        int flat = i * 256 + tid;
        float v = 0.f;
#pragma unroll
        for (int c = 0; c < 8; c++)
            v += g_part[((size_t)c * 128 + bh) * 4096 + flat];
        int d = flat >> 6, e = flat & 63;
        S[d * 68 + e] = v * 0.125f;
    }
    __syncthreads();

    if (tid < 64) {
        float m = -3.4e38f;
#pragma unroll
        for (int e = 0; e < 64; e++) m = fmaxf(m, S[tid * 68 + e]);
        float sum = 0.f;
#pragma unroll
        for (int e = 0; e < 64; e++) sum += __expf(S[tid * 68 + e] - m);
        mrow[tid] = m;
        irow[tid] = 1.f / sum;
    }
    __syncthreads();

    __nv_bfloat16* ah = g_ath + (size_t)bh * 4096;
    __nv_bfloat16* al = g_atl + (size_t)bh * 4096;
#pragma unroll
    for (int i = 0; i < 16; i++) {
        int flat = i * 256 + tid;
        int e = flat >> 6, d = flat & 63;
        float a = __expf(S[d * 68 + e] - mrow[d]) * irow[d];
        __nv_bfloat16 hi = __float2bfloat16(a);
        ah[flat] = hi;
        al[flat] = __float2bfloat16(a - __bfloat162float(hi));
    }
}

// ---------------------------------------------------------------------------
// K3: out[n,e] = sum_d v[n,d] * attn[d,e] via tensor cores.
// ---------------------------------------------------------------------------
__global__ __launch_bounds__(256) void out_mma_kernel(float* __restrict__ out)
{
    __shared__ __align__(128) uint8_t smem[49152];
    uint32_t sb = smem_u32(smem);
    const int tid  = threadIdx.x;
    const int wid  = tid >> 5;
    const int lane = tid & 31;
    const int bh   = blockIdx.y;
    const int b    = bh >> 4, h = bh & 15;
    const int nt0  = blockIdx.x * 128;

    const __nv_bfloat16* agh = g_ath + (size_t)bh * 4096;
    const __nv_bfloat16* agl = g_atl + (size_t)bh * 4096;
#pragma unroll
    for (int i = 0; i < 2; i++) {
        int slot = i * 256 + tid;
        int r = slot >> 3, c = slot & 7;
        uint32_t dst = (uint32_t)(r * 128 + ((c ^ (r & 7)) << 4));
        cp16(sb + 32768 + dst, agh + r * 64 + c * 8);
        cp16(sb + 40960 + dst, agl + r * 64 + c * 8);
    }
    const __nv_bfloat16* vgh = g_qkvh + ((size_t)b * SEQ + nt0) * N_TOT + 2 * D_HID + h * 64;
    const __nv_bfloat16* vgl = g_qkvl + ((size_t)b * SEQ + nt0) * N_TOT + 2 * D_HID + h * 64;
#pragma unroll
    for (int i = 0; i < 4; i++) {
        int slot = i * 256 + tid;
        int r = slot >> 3, c = slot & 7;
        uint32_t off = (uint32_t)(r * 128 + ((c ^ (r & 7)) << 4));
        cp16(sb + off,         vgh + (size_t)r * N_TOT + c * 8);
        cp16(sb + 16384 + off, vgl + (size_t)r * N_TOT + c * 8);
    }
    cp_commit();
    asm volatile("cp.async.wait_group 0;" ::: "memory");
    __syncthreads();

    const int wm = wid >> 1;
    const int wn = wid & 1;
    const int a_r0 = wm * 32 + (lane & 15);
    const int a_h  = lane >> 4;
    const int b_r0 = wn * 32 + ((lane >> 4) << 3) + (lane & 7);
    const int b_h  = (lane >> 3) & 1;

    float acc[2][4][4];
#pragma unroll
    for (int mt = 0; mt < 2; mt++)
#pragma unroll
        for (int nt = 0; nt < 4; nt++)
#pragma unroll
            for (int j = 0; j < 4; j++) acc[mt][nt][j] = 0.f;

#pragma unroll
    for (int ks = 0; ks < 4; ks++) {
        uint32_t avh[2][4], avl[2][4];
#pragma unroll
        for (int mt = 0; mt < 2; mt++) {
            int r   = a_r0 + mt * 16;
            int c16 = ks * 2 + a_h;
            uint32_t so = (uint32_t)(r * 128 + ((c16 ^ (r & 7)) << 4));
            ldsm4(avh[mt], sb + so);
            ldsm4(avl[mt], sb + 16384 + so);
        }
        uint32_t bah[4][2], bal[4][2];
#pragma unroll
        for (int np = 0; np < 2; np++) {
            int r   = b_r0 + np * 16;
            int c16 = ks * 2 + b_h;
            uint32_t so = (uint32_t)(r * 128 + ((c16 ^ (r & 7)) << 4));
            uint32_t q[4];
            ldsm4(q, sb + 32768 + so);
            bah[np * 2 + 0][0] = q[0]; bah[np * 2 + 0][1] = q[1];
            bah[np * 2 + 1][0] = q[2]; bah[np * 2 + 1][1] = q[3];
            ldsm4(q, sb + 40960 + so);
            bal[np * 2 + 0][0] = q[0]; bal[np * 2 + 0][1] = q[1];
            bal[np * 2 + 1][0] = q[2]; bal[np * 2 + 1][1] = q[3];
        }
#pragma unroll
        for (int mt = 0; mt < 2; mt++)
#pragma unroll
            for (int nt = 0; nt < 4; nt++) {
                mma16816(acc[mt][nt], avh[mt], bah[nt]);
                mma16816(acc[mt][nt], avh[mt], bal[nt]);
                mma16816(acc[mt][nt], avl[mt], bah[nt]);
            }
    }

#pragma unroll
    for (int mt = 0; mt < 2; mt++)
#pragma unroll
        for (int half = 0; half < 2; half++) {
            int n = nt0 + wm * 32 + mt * 16 + (lane >> 2) + half * 8;
            float* orow = out + ((size_t)b * SEQ + n) * D_HID + h * 64
                          + wn * 32 + (lane & 3) * 2;
#pragma unroll
            for (int nt = 0; nt < 4; nt++) {
                float2 v;
                v.x = acc[mt][nt][half * 2 + 0];
                v.y = acc[mt][nt][half * 2 + 1];
                *(float2*)(orow + nt * 8) = v;
            }
        }
}

// ---------------------------------------------------------------------------
extern "C" void kernel_launch(void* const* d_in, const int* in_sizes, int n_in,
                              void* d_out, int out_size)
{
    const float* x    = (const float*)d_in[0];
    const float* W    = (const float*)d_in[1];
    const float* bias = (const float*)d_in[2];
    float* out = (float*)d_out;

    convert_x_kernel<<<(M_TOT * K_TOT) / (256 * 8), 256>>>(x);
    convert_w_kernel<<<dim3(N_TOT / 32, K_TOT / 32), dim3(32, 8)>>>(W);

    cudaFuncSetAttribute(qkv_mma_kernel, cudaFuncAttributeMaxDynamicSharedMemorySize, GEMM_SMEM);
    qkv_mma_kernel<<<dim3(N_TOT / BN, M_TOT / BM), 384, GEMM_SMEM>>>(bias);

    cudaFuncSetAttribute(attn_part_kernel, cudaFuncAttributeMaxDynamicSharedMemorySize, K2_SMEM);
    attn_part_kernel<<<dim3(8, BATCH * N_HEADS), 256, K2_SMEM>>>();

    attn_softmax_kernel<<<BATCH * N_HEADS, 256>>>();

    out_mma_kernel<<<dim3(SEQ / 128, BATCH * N_HEADS), 256>>>(out);
}

// round 8
// speedup vs baseline: 1.0369x; 1.0369x over previous
#include <cuda_runtime.h>
#include <cuda_bf16.h>
#include <cstdint>

#define BATCH   8
#define SEQ     4096
#define D_HID   1024
#define N_HEADS 16
#define D_HEAD  64
#define M_TOT   (BATCH * SEQ)     // 32768
#define N_TOT   (3 * D_HID)       // 3072
#define K_TOT   (D_HID)           // 1024

// Scratch (allocation-free rule: __device__ globals)
__device__ __nv_bfloat16 g_qkvh[(size_t)M_TOT * N_TOT];   // qkv hi plane
__device__ __nv_bfloat16 g_qkvl[(size_t)M_TOT * N_TOT];   // qkv lo plane
__device__ float g_part[(size_t)8 * 128 * 4096];
__device__ __nv_bfloat16 g_ath[(size_t)128 * 4096];       // attn^T [bh][e][d] hi
__device__ __nv_bfloat16 g_atl[(size_t)128 * 4096];       // attn^T lo
__device__ __nv_bfloat16 g_xh[(size_t)M_TOT * K_TOT];
__device__ __nv_bfloat16 g_xl[(size_t)M_TOT * K_TOT];
__device__ __nv_bfloat16 g_wth[(size_t)N_TOT * K_TOT];
__device__ __nv_bfloat16 g_wtl[(size_t)N_TOT * K_TOT];

// ---------------------------------------------------------------------------
// helpers
// ---------------------------------------------------------------------------
__device__ __forceinline__ uint32_t smem_u32(const void* p) {
    uint32_t a;
    asm("{ .reg .u64 t; cvta.to.shared.u64 t, %1; cvt.u32.u64 %0, t; }" : "=r"(a) : "l"(p));
    return a;
}
__device__ __forceinline__ void cp16(uint32_t smem_dst, const void* gsrc) {
    asm volatile("cp.async.cg.shared.global [%0], [%1], 16;" :: "r"(smem_dst), "l"(gsrc));
}
__device__ __forceinline__ void cp_commit() {
    asm volatile("cp.async.commit_group;" ::: "memory");
}
__device__ __forceinline__ void ldsm4(uint32_t* r, uint32_t addr) {
    asm volatile("ldmatrix.sync.aligned.m8n8.x4.shared.b16 {%0,%1,%2,%3}, [%4];"
                 : "=r"(r[0]), "=r"(r[1]), "=r"(r[2]), "=r"(r[3]) : "r"(addr));
}
__device__ __forceinline__ void ldsm4t(uint32_t* r, uint32_t addr) {
    asm volatile("ldmatrix.sync.aligned.m8n8.x4.trans.shared.b16 {%0,%1,%2,%3}, [%4];"
                 : "=r"(r[0]), "=r"(r[1]), "=r"(r[2]), "=r"(r[3]) : "r"(addr));
}
__device__ __forceinline__ void mma16816(float* c, const uint32_t* a, const uint32_t* b) {
    asm volatile("mma.sync.aligned.m16n8k16.row.col.f32.bf16.bf16.f32 "
                 "{%0,%1,%2,%3}, {%4,%5,%6,%7}, {%8,%9}, {%0,%1,%2,%3};"
                 : "+f"(c[0]), "+f"(c[1]), "+f"(c[2]), "+f"(c[3])
                 : "r"(a[0]), "r"(a[1]), "r"(a[2]), "r"(a[3]), "r"(b[0]), "r"(b[1]));
}
__device__ __forceinline__ uint32_t pack_bf16(float x, float y) {
    __nv_bfloat162 t = __floats2bfloat162_rn(x, y);
    return *reinterpret_cast<uint32_t*>(&t);
}

// ---------------------------------------------------------------------------
// Conversion kernels (fp32 -> bf16 hi/lo split)
// ---------------------------------------------------------------------------
__global__ __launch_bounds__(256) void convert_x_kernel(const float* __restrict__ x)
{
    size_t i = ((size_t)blockIdx.x * 256 + threadIdx.x) * 8;
    float4 a = *(const float4*)(x + i);
    float4 b = *(const float4*)(x + i + 4);
    float v[8] = {a.x, a.y, a.z, a.w, b.x, b.y, b.z, b.w};
    __nv_bfloat16 hi[8], lo[8];
#pragma unroll
    for (int j = 0; j < 8; j++) {
        hi[j] = __float2bfloat16(v[j]);
        lo[j] = __float2bfloat16(v[j] - __bfloat162float(hi[j]));
    }
    *(uint4*)(g_xh + i) = *(uint4*)hi;
    *(uint4*)(g_xl + i) = *(uint4*)lo;
}

__global__ __launch_bounds__(256) void convert_w_kernel(const float* __restrict__ W)
{
    __shared__ float t[32][33];
    int x0 = blockIdx.x * 32;
    int y0 = blockIdx.y * 32;
    int tx = threadIdx.x, ty = threadIdx.y;
#pragma unroll
    for (int j = 0; j < 4; j++)
        t[ty + j * 8][tx] = W[(size_t)(y0 + ty + j * 8) * N_TOT + x0 + tx];
    __syncthreads();
#pragma unroll
    for (int j = 0; j < 4; j++) {
        int n = x0 + ty + j * 8;
        int k = y0 + tx;
        float v = t[tx][ty + j * 8];
        __nv_bfloat16 hi = __float2bfloat16(v);
        __nv_bfloat16 lo = __float2bfloat16(v - __bfloat162float(hi));
        g_wth[(size_t)n * K_TOT + k] = hi;
        g_wtl[(size_t)n * K_TOT + k] = lo;
    }
}

// ---------------------------------------------------------------------------
// K1: qkv = x @ W + b, mma.sync bf16 3-term split. 256x128, BK=64, 4 stages,
// 512 threads (16 warps, warp tile 32x64) — the measured-best round-5 config.
// Epilogue emits bf16 hi/lo planes.
// ---------------------------------------------------------------------------
#define BM 256
#define BN 128
#define BK 64
#define NCHUNK 48
#define STAGE_BYTES 49152
#define A_OFF(s) ((s) * STAGE_BYTES)
#define B_OFF(s) ((s) * STAGE_BYTES + 32768)
#define GEMM_SMEM (4 * STAGE_BYTES)    // 192 KB

__device__ __forceinline__ void load_chunk(uint32_t sb, int tid, int by, int bx, int c, int s)
{
    int seg  = c >> 4;
    int koff = (c & 15) * BK;
    const __nv_bfloat16* A = (seg == 2 ? g_xl : g_xh) + (size_t)(by * BM) * K_TOT + koff;
    const __nv_bfloat16* B = (seg == 1 ? g_wtl : g_wth) + (size_t)(bx * BN) * K_TOT + koff;
    uint32_t ab = sb + A_OFF(s), bb = sb + B_OFF(s);
#pragma unroll
    for (int i = 0; i < 4; i++) {            // A: 2048 slots
        int slot = i * 512 + tid;
        int r   = slot >> 3;
        int c16 = slot & 7;
        uint32_t off = (uint32_t)(r * 128 + ((c16 ^ (r & 7)) * 16));
        cp16(ab + off, A + (size_t)r * K_TOT + c16 * 8);
    }
#pragma unroll
    for (int i = 0; i < 2; i++) {            // B: 1024 slots
        int slot = i * 512 + tid;
        int r   = slot >> 3;
        int c16 = slot & 7;
        uint32_t off = (uint32_t)(r * 128 + ((c16 ^ (r & 7)) * 16));
        cp16(bb + off, B + (size_t)r * K_TOT + c16 * 8);
    }
}

__global__ __launch_bounds__(512, 1) void qkv_mma_kernel(const float* __restrict__ bias)
{
    extern __shared__ __align__(128) uint8_t smem[];
    uint32_t sb = smem_u32(smem);
    const int tid  = threadIdx.x;
    const int wid  = tid >> 5;
    const int lane = tid & 31;
    const int bx = blockIdx.x;    // N tile 0..23
    const int by = blockIdx.y;    // M tile 0..127
    const int wm = wid >> 1;      // 0..7  (32 M each)
    const int wn = wid & 1;       // 0..1  (64 N each)

    float acc[2][8][4];
#pragma unroll
    for (int mt = 0; mt < 2; mt++)
#pragma unroll
        for (int nt = 0; nt < 8; nt++)
#pragma unroll
            for (int j = 0; j < 4; j++) acc[mt][nt][j] = 0.f;

    load_chunk(sb, tid, by, bx, 0, 0); cp_commit();
    load_chunk(sb, tid, by, bx, 1, 1); cp_commit();
    load_chunk(sb, tid, by, bx, 2, 2); cp_commit();

    const int a_r = wm * 32 + (lane & 15);
    const int a_h = lane >> 4;
    const int b_r = wn * 64 + ((lane >> 4) << 3) + (lane & 7);
    const int b_h = (lane >> 3) & 1;

    for (int ch = 0; ch < NCHUNK; ch++) {
        const int s = ch & 3;
        asm volatile("cp.async.wait_group 2;" ::: "memory");
        __syncthreads();
        if (ch + 3 < NCHUNK) load_chunk(sb, tid, by, bx, ch + 3, (ch + 3) & 3);
        cp_commit();

        const uint32_t abase = sb + A_OFF(s);
        const uint32_t bbase = sb + B_OFF(s);
#pragma unroll
        for (int ks = 0; ks < 4; ks++) {
            uint32_t a[2][4];
#pragma unroll
            for (int mt = 0; mt < 2; mt++) {
                int r   = a_r + mt * 16;
                int c16 = ks * 2 + a_h;
                ldsm4(a[mt], abase + r * 128 + ((c16 ^ (r & 7)) * 16));
            }
            uint32_t b[8][2];
#pragma unroll
            for (int np = 0; np < 4; np++) {
                int r   = b_r + np * 16;
                int c16 = ks * 2 + b_h;
                uint32_t q[4];
                ldsm4(q, bbase + r * 128 + ((c16 ^ (r & 7)) * 16));
                b[np * 2 + 0][0] = q[0]; b[np * 2 + 0][1] = q[1];
                b[np * 2 + 1][0] = q[2]; b[np * 2 + 1][1] = q[3];
            }
#pragma unroll
            for (int mt = 0; mt < 2; mt++)
#pragma unroll
                for (int nt = 0; nt < 8; nt++)
                    mma16816(acc[mt][nt], a[mt], b[nt]);
        }
    }
    asm volatile("cp.async.wait_group 0;" ::: "memory");

    // Epilogue: +bias, split fp32 -> bf16 hi/lo planes
    const int ncol0 = bx * BN + wn * 64 + (lane & 3) * 2;
    float b0[8], b1[8];
#pragma unroll
    for (int nt = 0; nt < 8; nt++) {
        b0[nt] = __ldg(bias + ncol0 + nt * 8);
        b1[nt] = __ldg(bias + ncol0 + nt * 8 + 1);
    }
#pragma unroll
    for (int mt = 0; mt < 2; mt++)
#pragma unroll
        for (int half = 0; half < 2; half++) {
            int m = by * BM + wm * 32 + mt * 16 + (lane >> 2) + half * 8;
            size_t base = (size_t)m * N_TOT + ncol0;
#pragma unroll
            for (int nt = 0; nt < 8; nt++) {
                float vx = acc[mt][nt][half * 2 + 0] + b0[nt];
                float vy = acc[mt][nt][half * 2 + 1] + b1[nt];
                __nv_bfloat16 hx = __float2bfloat16(vx);
                __nv_bfloat16 hy = __float2bfloat16(vy);
                *(uint32_t*)(g_qkvh + base + nt * 8) = pack_bf16(vx, vy);
                *(uint32_t*)(g_qkvl + base + nt * 8) =
                    pack_bf16(vx - __bfloat162float(hx), vy - __bfloat162float(hy));
            }
        }
}

// ---------------------------------------------------------------------------
// K2a: partial S over a 512-n chunk, tensor cores, bf16 planes via ldmatrix.trans.
// grid (8, 128). 256 threads. Subtile 64n, 2-stage cp.async (64KB smem).
// ---------------------------------------------------------------------------
#define K2_SMEM 65536

__device__ __forceinline__ void k2_load_sub(uint32_t sb, int tid,
                                            const __nv_bfloat16* qh, const __nv_bfloat16* ql,
                                            const __nv_bfloat16* kh, const __nv_bfloat16* kl,
                                            int n0, int stg)
{
    const __nv_bfloat16* src[4] = {qh, ql, kh, kl};
    uint32_t base = sb + stg * 32768;
#pragma unroll
    for (int p = 0; p < 4; p++) {
#pragma unroll
        for (int i = 0; i < 2; i++) {
            int slot = i * 256 + tid;
            int r   = slot >> 3;
            int c16 = slot & 7;
            uint32_t off = (uint32_t)(r * 128 + ((c16 ^ (r & 7)) << 4));
            cp16(base + p * 8192 + off, src[p] + (size_t)(n0 + r) * N_TOT + c16 * 8);
        }
    }
}

__global__ __launch_bounds__(256) void attn_part_kernel()
{
    extern __shared__ __align__(128) uint8_t smem[];
    uint32_t sb = smem_u32(smem);
    const int tid   = threadIdx.x;
    const int wid   = tid >> 5;
    const int lane  = tid & 31;
    const int chunk = blockIdx.x;
    const int bh    = blockIdx.y;
    const int b     = bh >> 4, h = bh & 15;

    const __nv_bfloat16* qh = g_qkvh + (size_t)b * SEQ * N_TOT + h * 64;
    const __nv_bfloat16* ql = g_qkvl + (size_t)b * SEQ * N_TOT + h * 64;
    const __nv_bfloat16* kh = qh + D_HID;
    const __nv_bfloat16* kl = ql + D_HID;

    const int wm = wid >> 2;
    const int wn = wid & 3;

    const int an = ((lane >> 4) & 1) * 8 + (lane & 7);
    const int ac = ((lane >> 3) & 1);
    const int bn = ((lane >> 3) & 1) * 8 + (lane & 7);
    const int bc = wn * 2 + (lane >> 4);

    float acc[2][2][4];
#pragma unroll
    for (int mt = 0; mt < 2; mt++)
#pragma unroll
        for (int nt = 0; nt < 2; nt++)
#pragma unroll
            for (int j = 0; j < 4; j++) acc[mt][nt][j] = 0.f;

    const int nbase = chunk * 512;
    k2_load_sub(sb, tid, qh, ql, kh, kl, nbase, 0);
    cp_commit();

    for (int t = 0; t < 8; t++) {
        __syncthreads();
        if (t + 1 < 8) k2_load_sub(sb, tid, qh, ql, kh, kl, nbase + (t + 1) * 64, (t + 1) & 1);
        cp_commit();
        asm volatile("cp.async.wait_group 1;" ::: "memory");
        __syncthreads();

        uint32_t stg = sb + (t & 1) * 32768;
#pragma unroll
        for (int ks = 0; ks < 4; ks++) {
            uint32_t aqh[2][4], aql[2][4];
#pragma unroll
            for (int mt = 0; mt < 2; mt++) {
                int n   = ks * 16 + an;
                int c16 = wm * 4 + mt * 2 + ac;
                uint32_t off = (uint32_t)(n * 128 + ((c16 ^ (n & 7)) << 4));
                ldsm4t(aqh[mt], stg + off);
                ldsm4t(aql[mt], stg + 8192 + off);
            }
            uint32_t bkh[2][2], bkl[2][2];
            {
                int n   = ks * 16 + bn;
                uint32_t off = (uint32_t)(n * 128 + ((bc ^ (n & 7)) << 4));
                uint32_t q[4];
                ldsm4t(q, stg + 16384 + off);
                bkh[0][0] = q[0]; bkh[0][1] = q[1]; bkh[1][0] = q[2]; bkh[1][1] = q[3];
                ldsm4t(q, stg + 24576 + off);
                bkl[0][0] = q[0]; bkl[0][1] = q[1]; bkl[1][0] = q[2]; bkl[1][1] = q[3];
            }
#pragma unroll
            for (int mt = 0; mt < 2; mt++)
#pragma unroll
                for (int nt = 0; nt < 2; nt++) {
                    mma16816(acc[mt][nt], aqh[mt], bkh[nt]);
                    mma16816(acc[mt][nt], aqh[mt], bkl[nt]);
                    mma16816(acc[mt][nt], aql[mt], bkh[nt]);
                }
        }
    }

    float* pg = g_part + ((size_t)chunk * 128 + bh) * 4096;
#pragma unroll
    for (int mt = 0; mt < 2; mt++)
#pragma unroll
        for (int nt = 0; nt < 2; nt++)
#pragma unroll
            for (int half = 0; half < 2; half++) {
                int d = wm * 32 + mt * 16 + (lane >> 2) + half * 8;
                int e = wn * 16 + nt * 8 + (lane & 3) * 2;
                float2 v;
                v.x = acc[mt][nt][half * 2 + 0];
                v.y = acc[mt][nt][half * 2 + 1];
                *(float2*)(pg + d * 64 + e) = v;
            }
}

// ---------------------------------------------------------------------------
// K2b: reduce 8 partials, scale, softmax over e; emit attn^T bf16 hi/lo.
// ---------------------------------------------------------------------------
__global__ __launch_bounds__(256) void attn_softmax_kernel()
{
    __shared__ float S[64 * 68 + 128];
    float* mrow = S + 64 * 68;
    float* irow = mrow + 64;

    const int tid = threadIdx.x;
    const int bh  = blockIdx.x;

#pragma unroll
    for (int i = 0; i < 16; i++) {
        int flat = i * 256 + tid;
        float v = 0.f;
#pragma unroll
        for (int c = 0; c < 8; c++)
            v += g_part[((size_t)c * 128 + bh) * 4096 + flat];
        int d = flat >> 6, e = flat & 63;
        S[d * 68 + e] = v * 0.125f;
    }
    __syncthreads();

    if (tid < 64) {
        float m = -3.4e38f;
#pragma unroll
        for (int e = 0; e < 64; e++) m = fmaxf(m, S[tid * 68 + e]);
        float sum = 0.f;
#pragma unroll
        for (int e = 0; e < 64; e++) sum += __expf(S[tid * 68 + e] - m);
        mrow[tid] = m;
        irow[tid] = 1.f / sum;
    }
    __syncthreads();

    __nv_bfloat16* ah = g_ath + (size_t)bh * 4096;
    __nv_bfloat16* al = g_atl + (size_t)bh * 4096;
#pragma unroll
    for (int i = 0; i < 16; i++) {
        int flat = i * 256 + tid;
        int e = flat >> 6, d = flat & 63;
        float a = __expf(S[d * 68 + e] - mrow[d]) * irow[d];
        __nv_bfloat16 hi = __float2bfloat16(a);
        ah[flat] = hi;
        al[flat] = __float2bfloat16(a - __bfloat162float(hi));
    }
}

// ---------------------------------------------------------------------------
// K3: out[n,e] = sum_d v[n,d] * attn[d,e] via tensor cores.
// ---------------------------------------------------------------------------
__global__ __launch_bounds__(256) void out_mma_kernel(float* __restrict__ out)
{
    __shared__ __align__(128) uint8_t smem[49152];
    uint32_t sb = smem_u32(smem);
    const int tid  = threadIdx.x;
    const int wid  = tid >> 5;
    const int lane = tid & 31;
    const int bh   = blockIdx.y;
    const int b    = bh >> 4, h = bh & 15;
    const int nt0  = blockIdx.x * 128;

    const __nv_bfloat16* agh = g_ath + (size_t)bh * 4096;
    const __nv_bfloat16* agl = g_atl + (size_t)bh * 4096;
#pragma unroll
    for (int i = 0; i < 2; i++) {
        int slot = i * 256 + tid;
        int r = slot >> 3, c = slot & 7;
        uint32_t dst = (uint32_t)(r * 128 + ((c ^ (r & 7)) << 4));
        cp16(sb + 32768 + dst, agh + r * 64 + c * 8);
        cp16(sb + 40960 + dst, agl + r * 64 + c * 8);
    }
    const __nv_bfloat16* vgh = g_qkvh + ((size_t)b * SEQ + nt0) * N_TOT + 2 * D_HID + h * 64;
    const __nv_bfloat16* vgl = g_qkvl + ((size_t)b * SEQ + nt0) * N_TOT + 2 * D_HID + h * 64;
#pragma unroll
    for (int i = 0; i < 4; i++) {
        int slot = i * 256 + tid;
        int r = slot >> 3, c = slot & 7;
        uint32_t off = (uint32_t)(r * 128 + ((c ^ (r & 7)) << 4));
        cp16(sb + off,         vgh + (size_t)r * N_TOT + c * 8);
        cp16(sb + 16384 + off, vgl + (size_t)r * N_TOT + c * 8);
    }
    cp_commit();
    asm volatile("cp.async.wait_group 0;" ::: "memory");
    __syncthreads();

    const int wm = wid >> 1;
    const int wn = wid & 1;
    const int a_r0 = wm * 32 + (lane & 15);
    const int a_h  = lane >> 4;
    const int b_r0 = wn * 32 + ((lane >> 4) << 3) + (lane & 7);
    const int b_h  = (lane >> 3) & 1;

    float acc[2][4][4];
#pragma unroll
    for (int mt = 0; mt < 2; mt++)
#pragma unroll
        for (int nt = 0; nt < 4; nt++)
#pragma unroll
            for (int j = 0; j < 4; j++) acc[mt][nt][j] = 0.f;

#pragma unroll
    for (int ks = 0; ks < 4; ks++) {
        uint32_t avh[2][4], avl[2][4];
#pragma unroll
        for (int mt = 0; mt < 2; mt++) {
            int r   = a_r0 + mt * 16;
            int c16 = ks * 2 + a_h;
            uint32_t so = (uint32_t)(r * 128 + ((c16 ^ (r & 7)) << 4));
            ldsm4(avh[mt], sb + so);
            ldsm4(avl[mt], sb + 16384 + so);
        }
        uint32_t bah[4][2], bal[4][2];
#pragma unroll
        for (int np = 0; np < 2; np++) {
            int r   = b_r0 + np * 16;
            int c16 = ks * 2 + b_h;
            uint32_t so = (uint32_t)(r * 128 + ((c16 ^ (r & 7)) << 4));
            uint32_t q[4];
            ldsm4(q, sb + 32768 + so);
            bah[np * 2 + 0][0] = q[0]; bah[np * 2 + 0][1] = q[1];
            bah[np * 2 + 1][0] = q[2]; bah[np * 2 + 1][1] = q[3];
            ldsm4(q, sb + 40960 + so);
            bal[np * 2 + 0][0] = q[0]; bal[np * 2 + 0][1] = q[1];
            bal[np * 2 + 1][0] = q[2]; bal[np * 2 + 1][1] = q[3];
        }
#pragma unroll
        for (int mt = 0; mt < 2; mt++)
#pragma unroll
            for (int nt = 0; nt < 4; nt++) {
                mma16816(acc[mt][nt], avh[mt], bah[nt]);
                mma16816(acc[mt][nt], avh[mt], bal[nt]);
                mma16816(acc[mt][nt], avl[mt], bah[nt]);
            }
    }

#pragma unroll
    for (int mt = 0; mt < 2; mt++)
#pragma unroll
        for (int half = 0; half < 2; half++) {
            int n = nt0 + wm * 32 + mt * 16 + (lane >> 2) + half * 8;
            float* orow = out + ((size_t)b * SEQ + n) * D_HID + h * 64
                          + wn * 32 + (lane & 3) * 2;
#pragma unroll
            for (int nt = 0; nt < 4; nt++) {
                float2 v;
                v.x = acc[mt][nt][half * 2 + 0];
                v.y = acc[mt][nt][half * 2 + 1];
                *(float2*)(orow + nt * 8) = v;
            }
        }
}

// ---------------------------------------------------------------------------
extern "C" void kernel_launch(void* const* d_in, const int* in_sizes, int n_in,
                              void* d_out, int out_size)
{
    const float* x    = (const float*)d_in[0];
    const float* W    = (const float*)d_in[1];
    const float* bias = (const float*)d_in[2];
    float* out = (float*)d_out;

    convert_x_kernel<<<(M_TOT * K_TOT) / (256 * 8), 256>>>(x);
    convert_w_kernel<<<dim3(N_TOT / 32, K_TOT / 32), dim3(32, 8)>>>(W);

    cudaFuncSetAttribute(qkv_mma_kernel, cudaFuncAttributeMaxDynamicSharedMemorySize, GEMM_SMEM);
    qkv_mma_kernel<<<dim3(N_TOT / BN, M_TOT / BM), 512, GEMM_SMEM>>>(bias);

    cudaFuncSetAttribute(attn_part_kernel, cudaFuncAttributeMaxDynamicSharedMemorySize, K2_SMEM);
    attn_part_kernel<<<dim3(8, BATCH * N_HEADS), 256, K2_SMEM>>>();

    attn_softmax_kernel<<<BATCH * N_HEADS, 256>>>();

    out_mma_kernel<<<dim3(SEQ / 128, BATCH * N_HEADS), 256>>>(out);
}

// round 9
// speedup vs baseline: 1.0919x; 1.0530x over previous
#include <cuda_runtime.h>
#include <cuda_bf16.h>
#include <cstdint>

#define BATCH   8
#define SEQ     4096
#define D_HID   1024
#define N_HEADS 16
#define D_HEAD  64
#define M_TOT   (BATCH * SEQ)     // 32768
#define N_TOT   (3 * D_HID)       // 3072
#define K_TOT   (D_HID)           // 1024

// Scratch (allocation-free rule: __device__ globals)
__device__ __nv_bfloat16 g_qkvh[(size_t)M_TOT * N_TOT];   // qkv hi plane
__device__ __nv_bfloat16 g_qkvl[(size_t)M_TOT * N_TOT];   // qkv lo plane
__device__ float g_part[(size_t)8 * 128 * 4096];
__device__ __nv_bfloat16 g_ath[(size_t)128 * 4096];       // attn^T [bh][e][d] hi
__device__ __nv_bfloat16 g_atl[(size_t)128 * 4096];       // attn^T lo
__device__ __nv_bfloat16 g_xh[(size_t)M_TOT * K_TOT];
__device__ __nv_bfloat16 g_xl[(size_t)M_TOT * K_TOT];
__device__ __nv_bfloat16 g_wth[(size_t)N_TOT * K_TOT];
__device__ __nv_bfloat16 g_wtl[(size_t)N_TOT * K_TOT];

// ---------------------------------------------------------------------------
// helpers
// ---------------------------------------------------------------------------
__device__ __forceinline__ uint32_t smem_u32(const void* p) {
    uint32_t a;
    asm("{ .reg .u64 t; cvta.to.shared.u64 t, %1; cvt.u32.u64 %0, t; }" : "=r"(a) : "l"(p));
    return a;
}
__device__ __forceinline__ void cp16(uint32_t smem_dst, const void* gsrc) {
    asm volatile("cp.async.cg.shared.global [%0], [%1], 16;" :: "r"(smem_dst), "l"(gsrc));
}
__device__ __forceinline__ void cp_commit() {
    asm volatile("cp.async.commit_group;" ::: "memory");
}
__device__ __forceinline__ void ldsm4(uint32_t* r, uint32_t addr) {
    asm volatile("ldmatrix.sync.aligned.m8n8.x4.shared.b16 {%0,%1,%2,%3}, [%4];"
                 : "=r"(r[0]), "=r"(r[1]), "=r"(r[2]), "=r"(r[3]) : "r"(addr));
}
__device__ __forceinline__ void ldsm4t(uint32_t* r, uint32_t addr) {
    asm volatile("ldmatrix.sync.aligned.m8n8.x4.trans.shared.b16 {%0,%1,%2,%3}, [%4];"
                 : "=r"(r[0]), "=r"(r[1]), "=r"(r[2]), "=r"(r[3]) : "r"(addr));
}
__device__ __forceinline__ void mma16816(float* c, const uint32_t* a, const uint32_t* b) {
    asm volatile("mma.sync.aligned.m16n8k16.row.col.f32.bf16.bf16.f32 "
                 "{%0,%1,%2,%3}, {%4,%5,%6,%7}, {%8,%9}, {%0,%1,%2,%3};"
                 : "+f"(c[0]), "+f"(c[1]), "+f"(c[2]), "+f"(c[3])
                 : "r"(a[0]), "r"(a[1]), "r"(a[2]), "r"(a[3]), "r"(b[0]), "r"(b[1]));
}
__device__ __forceinline__ uint32_t pack_bf16(float x, float y) {
    __nv_bfloat162 t = __floats2bfloat162_rn(x, y);
    return *reinterpret_cast<uint32_t*>(&t);
}

// ---------------------------------------------------------------------------
// Conversion kernels (fp32 -> bf16 hi/lo split)
// ---------------------------------------------------------------------------
__global__ __launch_bounds__(256) void convert_x_kernel(const float* __restrict__ x)
{
    size_t i = ((size_t)blockIdx.x * 256 + threadIdx.x) * 8;
    float4 a = *(const float4*)(x + i);
    float4 b = *(const float4*)(x + i + 4);
    float v[8] = {a.x, a.y, a.z, a.w, b.x, b.y, b.z, b.w};
    __nv_bfloat16 hi[8], lo[8];
#pragma unroll
    for (int j = 0; j < 8; j++) {
        hi[j] = __float2bfloat16(v[j]);
        lo[j] = __float2bfloat16(v[j] - __bfloat162float(hi[j]));
    }
    *(uint4*)(g_xh + i) = *(uint4*)hi;
    *(uint4*)(g_xl + i) = *(uint4*)lo;
}

__global__ __launch_bounds__(256) void convert_w_kernel(const float* __restrict__ W)
{
    __shared__ float t[32][33];
    int x0 = blockIdx.x * 32;
    int y0 = blockIdx.y * 32;
    int tx = threadIdx.x, ty = threadIdx.y;
#pragma unroll
    for (int j = 0; j < 4; j++)
        t[ty + j * 8][tx] = W[(size_t)(y0 + ty + j * 8) * N_TOT + x0 + tx];
    __syncthreads();
#pragma unroll
    for (int j = 0; j < 4; j++) {
        int n = x0 + ty + j * 8;
        int k = y0 + tx;
        float v = t[tx][ty + j * 8];
        __nv_bfloat16 hi = __float2bfloat16(v);
        __nv_bfloat16 lo = __float2bfloat16(v - __bfloat162float(hi));
        g_wth[(size_t)n * K_TOT + k] = hi;
        g_wtl[(size_t)n * K_TOT + k] = lo;
    }
}

// ---------------------------------------------------------------------------
// K1: qkv = x @ W + b, mma.sync bf16 3-term split. 256x128, BK=64, 4 stages,
// 512 threads (16 warps, warp tile 32x64). Epilogue stages hi/lo bf16 tiles
// through smem for fully-coalesced 16B global stores.
// ---------------------------------------------------------------------------
#define BM 256
#define BN 128
#define BK 64
#define NCHUNK 48
#define STAGE_BYTES 49152
#define A_OFF(s) ((s) * STAGE_BYTES)
#define B_OFF(s) ((s) * STAGE_BYTES + 32768)
#define GEMM_SMEM (4 * STAGE_BYTES)    // 192 KB

__device__ __forceinline__ void load_chunk(uint32_t sb, int tid, int by, int bx, int c, int s)
{
    int seg  = c >> 4;
    int koff = (c & 15) * BK;
    const __nv_bfloat16* A = (seg == 2 ? g_xl : g_xh) + (size_t)(by * BM) * K_TOT + koff;
    const __nv_bfloat16* B = (seg == 1 ? g_wtl : g_wth) + (size_t)(bx * BN) * K_TOT + koff;
    uint32_t ab = sb + A_OFF(s), bb = sb + B_OFF(s);
#pragma unroll
    for (int i = 0; i < 4; i++) {            // A: 2048 slots
        int slot = i * 512 + tid;
        int r   = slot >> 3;
        int c16 = slot & 7;
        uint32_t off = (uint32_t)(r * 128 + ((c16 ^ (r & 7)) * 16));
        cp16(ab + off, A + (size_t)r * K_TOT + c16 * 8);
    }
#pragma unroll
    for (int i = 0; i < 2; i++) {            // B: 1024 slots
        int slot = i * 512 + tid;
        int r   = slot >> 3;
        int c16 = slot & 7;
        uint32_t off = (uint32_t)(r * 128 + ((c16 ^ (r & 7)) * 16));
        cp16(bb + off, B + (size_t)r * K_TOT + c16 * 8);
    }
}

__global__ __launch_bounds__(512, 1) void qkv_mma_kernel(const float* __restrict__ bias)
{
    extern __shared__ __align__(128) uint8_t smem[];
    uint32_t sb = smem_u32(smem);
    const int tid  = threadIdx.x;
    const int wid  = tid >> 5;
    const int lane = tid & 31;
    const int bx = blockIdx.x;    // N tile 0..23
    const int by = blockIdx.y;    // M tile 0..127
    const int wm = wid >> 1;      // 0..7  (32 M each)
    const int wn = wid & 1;       // 0..1  (64 N each)

    float acc[2][8][4];
#pragma unroll
    for (int mt = 0; mt < 2; mt++)
#pragma unroll
        for (int nt = 0; nt < 8; nt++)
#pragma unroll
            for (int j = 0; j < 4; j++) acc[mt][nt][j] = 0.f;

    load_chunk(sb, tid, by, bx, 0, 0); cp_commit();
    load_chunk(sb, tid, by, bx, 1, 1); cp_commit();
    load_chunk(sb, tid, by, bx, 2, 2); cp_commit();

    const int a_r = wm * 32 + (lane & 15);
    const int a_h = lane >> 4;
    const int b_r = wn * 64 + ((lane >> 4) << 3) + (lane & 7);
    const int b_h = (lane >> 3) & 1;

    for (int ch = 0; ch < NCHUNK; ch++) {
        const int s = ch & 3;
        asm volatile("cp.async.wait_group 2;" ::: "memory");
        __syncthreads();
        if (ch + 3 < NCHUNK) load_chunk(sb, tid, by, bx, ch + 3, (ch + 3) & 3);
        cp_commit();

        const uint32_t abase = sb + A_OFF(s);
        const uint32_t bbase = sb + B_OFF(s);
#pragma unroll
        for (int ks = 0; ks < 4; ks++) {
            uint32_t a[2][4];
#pragma unroll
            for (int mt = 0; mt < 2; mt++) {
                int r   = a_r + mt * 16;
                int c16 = ks * 2 + a_h;
                ldsm4(a[mt], abase + r * 128 + ((c16 ^ (r & 7)) * 16));
            }
            uint32_t b[8][2];
#pragma unroll
            for (int np = 0; np < 4; np++) {
                int r   = b_r + np * 16;
                int c16 = ks * 2 + b_h;
                uint32_t q[4];
                ldsm4(q, bbase + r * 128 + ((c16 ^ (r & 7)) * 16));
                b[np * 2 + 0][0] = q[0]; b[np * 2 + 0][1] = q[1];
                b[np * 2 + 1][0] = q[2]; b[np * 2 + 1][1] = q[3];
            }
#pragma unroll
            for (int mt = 0; mt < 2; mt++)
#pragma unroll
                for (int nt = 0; nt < 8; nt++)
                    mma16816(acc[mt][nt], a[mt], b[nt]);
        }
    }
    asm volatile("cp.async.wait_group 0;" ::: "memory");
    __syncthreads();   // all warps done with stage smem before epilogue reuse

    // ---- Epilogue via smem staging ----
    // smem: hi tile [256][128] bf16 at 0 (row 256B, 16B-chunk XOR swizzle),
    //       lo tile at 65536.
    const int ncol0 = bx * BN + wn * 64 + (lane & 3) * 2;
    float b0[8], b1[8];
#pragma unroll
    for (int nt = 0; nt < 8; nt++) {
        b0[nt] = __ldg(bias + ncol0 + nt * 8);
        b1[nt] = __ldg(bias + ncol0 + nt * 8 + 1);
    }
#pragma unroll
    for (int mt = 0; mt < 2; mt++)
#pragma unroll
        for (int half = 0; half < 2; half++) {
            int m = wm * 32 + mt * 16 + (lane >> 2) + half * 8;   // 0..255 (local)
#pragma unroll
            for (int nt = 0; nt < 8; nt++) {
                float vx = acc[mt][nt][half * 2 + 0] + b0[nt];
                float vy = acc[mt][nt][half * 2 + 1] + b1[nt];
                __nv_bfloat16 hx = __float2bfloat16(vx);
                __nv_bfloat16 hy = __float2bfloat16(vy);
                int chunk = wn * 8 + nt;                          // 0..15
                uint32_t off = (uint32_t)(m * 256 + (((chunk ^ (m & 7)) << 4))
                                          + (lane & 3) * 4);
                *(uint32_t*)(smem + off) = pack_bf16(vx, vy);
                *(uint32_t*)(smem + 65536 + off) =
                    pack_bf16(vx - __bfloat162float(hx), vy - __bfloat162float(hy));
            }
        }
    __syncthreads();

    // coalesced store: 16B per thread, 16 threads cover one 256B row
#pragma unroll
    for (int i = 0; i < 8; i++) {
        int slot = i * 512 + tid;           // 0..4095
        int r = slot >> 4;                  // 0..255
        int c = slot & 15;                  // 16B chunk
        uint32_t soff = (uint32_t)(r * 256 + ((c ^ (r & 7)) << 4));
        uint4 hv = *(uint4*)(smem + soff);
        uint4 lv = *(uint4*)(smem + 65536 + soff);
        size_t gbase = (size_t)(by * BM + r) * N_TOT + bx * BN + c * 8;
        *(uint4*)(g_qkvh + gbase) = hv;
        *(uint4*)(g_qkvl + gbase) = lv;
    }
}

// ---------------------------------------------------------------------------
// K2a: partial S over a 512-n chunk, tensor cores, bf16 planes via ldmatrix.trans.
// grid (8, 128). 256 threads. Subtile 64n, 2-stage cp.async (64KB smem).
// ---------------------------------------------------------------------------
#define K2_SMEM 65536

__device__ __forceinline__ void k2_load_sub(uint32_t sb, int tid,
                                            const __nv_bfloat16* qh, const __nv_bfloat16* ql,
                                            const __nv_bfloat16* kh, const __nv_bfloat16* kl,
                                            int n0, int stg)
{
    const __nv_bfloat16* src[4] = {qh, ql, kh, kl};
    uint32_t base = sb + stg * 32768;
#pragma unroll
    for (int p = 0; p < 4; p++) {
#pragma unroll
        for (int i = 0; i < 2; i++) {
            int slot = i * 256 + tid;
            int r   = slot >> 3;
            int c16 = slot & 7;
            uint32_t off = (uint32_t)(r * 128 + ((c16 ^ (r & 7)) << 4));
            cp16(base + p * 8192 + off, src[p] + (size_t)(n0 + r) * N_TOT + c16 * 8);
        }
    }
}

__global__ __launch_bounds__(256) void attn_part_kernel()
{
    extern __shared__ __align__(128) uint8_t smem[];
    uint32_t sb = smem_u32(smem);
    const int tid   = threadIdx.x;
    const int wid   = tid >> 5;
    const int lane  = tid & 31;
    const int chunk = blockIdx.x;
    const int bh    = blockIdx.y;
    const int b     = bh >> 4, h = bh & 15;

    const __nv_bfloat16* qh = g_qkvh + (size_t)b * SEQ * N_TOT + h * 64;
    const __nv_bfloat16* ql = g_qkvl + (size_t)b * SEQ * N_TOT + h * 64;
    const __nv_bfloat16* kh = qh + D_HID;
    const __nv_bfloat16* kl = ql + D_HID;

    const int wm = wid >> 2;
    const int wn = wid & 3;

    const int an = ((lane >> 4) & 1) * 8 + (lane & 7);
    const int ac = ((lane >> 3) & 1);
    const int bn = ((lane >> 3) & 1) * 8 + (lane & 7);
    const int bc = wn * 2 + (lane >> 4);

    float acc[2][2][4];
#pragma unroll
    for (int mt = 0; mt < 2; mt++)
#pragma unroll
        for (int nt = 0; nt < 2; nt++)
#pragma unroll
            for (int j = 0; j < 4; j++) acc[mt][nt][j] = 0.f;

    const int nbase = chunk * 512;
    k2_load_sub(sb, tid, qh, ql, kh, kl, nbase, 0);
    cp_commit();

    for (int t = 0; t < 8; t++) {
        __syncthreads();
        if (t + 1 < 8) k2_load_sub(sb, tid, qh, ql, kh, kl, nbase + (t + 1) * 64, (t + 1) & 1);
        cp_commit();
        asm volatile("cp.async.wait_group 1;" ::: "memory");
        __syncthreads();

        uint32_t stg = sb + (t & 1) * 32768;
#pragma unroll
        for (int ks = 0; ks < 4; ks++) {
            uint32_t aqh[2][4], aql[2][4];
#pragma unroll
            for (int mt = 0; mt < 2; mt++) {
                int n   = ks * 16 + an;
                int c16 = wm * 4 + mt * 2 + ac;
                uint32_t off = (uint32_t)(n * 128 + ((c16 ^ (n & 7)) << 4));
                ldsm4t(aqh[mt], stg + off);
                ldsm4t(aql[mt], stg + 8192 + off);
            }
            uint32_t bkh[2][2], bkl[2][2];
            {
                int n   = ks * 16 + bn;
                uint32_t off = (uint32_t)(n * 128 + ((bc ^ (n & 7)) << 4));
                uint32_t q[4];
                ldsm4t(q, stg + 16384 + off);
                bkh[0][0] = q[0]; bkh[0][1] = q[1]; bkh[1][0] = q[2]; bkh[1][1] = q[3];
                ldsm4t(q, stg + 24576 + off);
                bkl[0][0] = q[0]; bkl[0][1] = q[1]; bkl[1][0] = q[2]; bkl[1][1] = q[3];
            }
#pragma unroll
            for (int mt = 0; mt < 2; mt++)
#pragma unroll
                for (int nt = 0; nt < 2; nt++) {
                    mma16816(acc[mt][nt], aqh[mt], bkh[nt]);
                    mma16816(acc[mt][nt], aqh[mt], bkl[nt]);
                    mma16816(acc[mt][nt], aql[mt], bkh[nt]);
                }
        }
    }

    float* pg = g_part + ((size_t)chunk * 128 + bh) * 4096;
#pragma unroll
    for (int mt = 0; mt < 2; mt++)
#pragma unroll
        for (int nt = 0; nt < 2; nt++)
#pragma unroll
            for (int half = 0; half < 2; half++) {
                int d = wm * 32 + mt * 16 + (lane >> 2) + half * 8;
                int e = wn * 16 + nt * 8 + (lane & 3) * 2;
                float2 v;
                v.x = acc[mt][nt][half * 2 + 0];
                v.y = acc[mt][nt][half * 2 + 1];
                *(float2*)(pg + d * 64 + e) = v;
            }
}

// ---------------------------------------------------------------------------
// K2b: reduce 8 partials, scale, softmax over e; emit attn^T bf16 hi/lo.
// ---------------------------------------------------------------------------
__global__ __launch_bounds__(256) void attn_softmax_kernel()
{
    __shared__ float S[64 * 68 + 128];
    float* mrow = S + 64 * 68;
    float* irow = mrow + 64;

    const int tid = threadIdx.x;
    const int bh  = blockIdx.x;

#pragma unroll
    for (int i = 0; i < 16; i++) {
        int flat = i * 256 + tid;
        float v = 0.f;
#pragma unroll
        for (int c = 0; c < 8; c++)
            v += g_part[((size_t)c * 128 + bh) * 4096 + flat];
        int d = flat >> 6, e = flat & 63;
        S[d * 68 + e] = v * 0.125f;
    }
    __syncthreads();

    if (tid < 64) {
        float m = -3.4e38f;
#pragma unroll
        for (int e = 0; e < 64; e++) m = fmaxf(m, S[tid * 68 + e]);
        float sum = 0.f;
#pragma unroll
        for (int e = 0; e < 64; e++) sum += __expf(S[tid * 68 + e] - m);
        mrow[tid] = m;
        irow[tid] = 1.f / sum;
    }
    __syncthreads();

    __nv_bfloat16* ah = g_ath + (size_t)bh * 4096;
    __nv_bfloat16* al = g_atl + (size_t)bh * 4096;
#pragma unroll
    for (int i = 0; i < 16; i++) {
        int flat = i * 256 + tid;
        int e = flat >> 6, d = flat & 63;
        float a = __expf(S[d * 68 + e] - mrow[d]) * irow[d];
        __nv_bfloat16 hi = __float2bfloat16(a);
        ah[flat] = hi;
        al[flat] = __float2bfloat16(a - __bfloat162float(hi));
    }
}

// ---------------------------------------------------------------------------
// K3: out[n,e] = sum_d v[n,d] * attn[d,e] via tensor cores.
// ---------------------------------------------------------------------------
__global__ __launch_bounds__(256) void out_mma_kernel(float* __restrict__ out)
{
    __shared__ __align__(128) uint8_t smem[49152];
    uint32_t sb = smem_u32(smem);
    const int tid  = threadIdx.x;
    const int wid  = tid >> 5;
    const int lane = tid & 31;
    const int bh   = blockIdx.y;
    const int b    = bh >> 4, h = bh & 15;
    const int nt0  = blockIdx.x * 128;

    const __nv_bfloat16* agh = g_ath + (size_t)bh * 4096;
    const __nv_bfloat16* agl = g_atl + (size_t)bh * 4096;
#pragma unroll
    for (int i = 0; i < 2; i++) {
        int slot = i * 256 + tid;
        int r = slot >> 3, c = slot & 7;
        uint32_t dst = (uint32_t)(r * 128 + ((c ^ (r & 7)) << 4));
        cp16(sb + 32768 + dst, agh + r * 64 + c * 8);
        cp16(sb + 40960 + dst, agl + r * 64 + c * 8);
    }
    const __nv_bfloat16* vgh = g_qkvh + ((size_t)b * SEQ + nt0) * N_TOT + 2 * D_HID + h * 64;
    const __nv_bfloat16* vgl = g_qkvl + ((size_t)b * SEQ + nt0) * N_TOT + 2 * D_HID + h * 64;
#pragma unroll
    for (int i = 0; i < 4; i++) {
        int slot = i * 256 + tid;
        int r = slot >> 3, c = slot & 7;
        uint32_t off = (uint32_t)(r * 128 + ((c ^ (r & 7)) << 4));
        cp16(sb + off,         vgh + (size_t)r * N_TOT + c * 8);
        cp16(sb + 16384 + off, vgl + (size_t)r * N_TOT + c * 8);
    }
    cp_commit();
    asm volatile("cp.async.wait_group 0;" ::: "memory");
    __syncthreads();

    const int wm = wid >> 1;
    const int wn = wid & 1;
    const int a_r0 = wm * 32 + (lane & 15);
    const int a_h  = lane >> 4;
    const int b_r0 = wn * 32 + ((lane >> 4) << 3) + (lane & 7);
    const int b_h  = (lane >> 3) & 1;

    float acc[2][4][4];
#pragma unroll
    for (int mt = 0; mt < 2; mt++)
#pragma unroll
        for (int nt = 0; nt < 4; nt++)
#pragma unroll
            for (int j = 0; j < 4; j++) acc[mt][nt][j] = 0.f;

#pragma unroll
    for (int ks = 0; ks < 4; ks++) {
        uint32_t avh[2][4], avl[2][4];
#pragma unroll
        for (int mt = 0; mt < 2; mt++) {
            int r   = a_r0 + mt * 16;
            int c16 = ks * 2 + a_h;
            uint32_t so = (uint32_t)(r * 128 + ((c16 ^ (r & 7)) << 4));
            ldsm4(avh[mt], sb + so);
            ldsm4(avl[mt], sb + 16384 + so);
        }
        uint32_t bah[4][2], bal[4][2];
#pragma unroll
        for (int np = 0; np < 2; np++) {
            int r   = b_r0 + np * 16;
            int c16 = ks * 2 + b_h;
            uint32_t so = (uint32_t)(r * 128 + ((c16 ^ (r & 7)) << 4));
            uint32_t q[4];
            ldsm4(q, sb + 32768 + so);
            bah[np * 2 + 0][0] = q[0]; bah[np * 2 + 0][1] = q[1];
            bah[np * 2 + 1][0] = q[2]; bah[np * 2 + 1][1] = q[3];
            ldsm4(q, sb + 40960 + so);
            bal[np * 2 + 0][0] = q[0]; bal[np * 2 + 0][1] = q[1];
            bal[np * 2 + 1][0] = q[2]; bal[np * 2 + 1][1] = q[3];
        }
#pragma unroll
        for (int mt = 0; mt < 2; mt++)
#pragma unroll
            for (int nt = 0; nt < 4; nt++) {
                mma16816(acc[mt][nt], avh[mt], bah[nt]);
                mma16816(acc[mt][nt], avh[mt], bal[nt]);
                mma16816(acc[mt][nt], avl[mt], bah[nt]);
            }
    }

#pragma unroll
    for (int mt = 0; mt < 2; mt++)
#pragma unroll
        for (int half = 0; half < 2; half++) {
            int n = nt0 + wm * 32 + mt * 16 + (lane >> 2) + half * 8;
            float* orow = out + ((size_t)b * SEQ + n) * D_HID + h * 64
                          + wn * 32 + (lane & 3) * 2;
#pragma unroll
            for (int nt = 0; nt < 4; nt++) {
                float2 v;
                v.x = acc[mt][nt][half * 2 + 0];
                v.y = acc[mt][nt][half * 2 + 1];
                *(float2*)(orow + nt * 8) = v;
            }
        }
}

// ---------------------------------------------------------------------------
extern "C" void kernel_launch(void* const* d_in, const int* in_sizes, int n_in,
                              void* d_out, int out_size)
{
    const float* x    = (const float*)d_in[0];
    const float* W    = (const float*)d_in[1];
    const float* bias = (const float*)d_in[2];
    float* out = (float*)d_out;

    convert_x_kernel<<<(M_TOT * K_TOT) / (256 * 8), 256>>>(x);
    convert_w_kernel<<<dim3(N_TOT / 32, K_TOT / 32), dim3(32, 8)>>>(W);

    cudaFuncSetAttribute(qkv_mma_kernel, cudaFuncAttributeMaxDynamicSharedMemorySize, GEMM_SMEM);
    qkv_mma_kernel<<<dim3(N_TOT / BN, M_TOT / BM), 512, GEMM_SMEM>>>(bias);

    cudaFuncSetAttribute(attn_part_kernel, cudaFuncAttributeMaxDynamicSharedMemorySize, K2_SMEM);
    attn_part_kernel<<<dim3(8, BATCH * N_HEADS), 256, K2_SMEM>>>();

    attn_softmax_kernel<<<BATCH * N_HEADS, 256>>>();

    out_mma_kernel<<<dim3(SEQ / 128, BATCH * N_HEADS), 256>>>(out);
}

// round 10
// speedup vs baseline: 1.1497x; 1.0530x over previous
#include <cuda_runtime.h>
#include <cuda_bf16.h>
#include <cstdint>

#define BATCH   8
#define SEQ     4096
#define D_HID   1024
#define N_HEADS 16
#define D_HEAD  64
#define M_TOT   (BATCH * SEQ)     // 32768
#define N_TOT   (3 * D_HID)       // 3072
#define K_TOT   (D_HID)           // 1024

// Scratch (allocation-free rule: __device__ globals)
__device__ __nv_bfloat16 g_qkvh[(size_t)M_TOT * N_TOT];   // qkv hi plane
__device__ __nv_bfloat16 g_qkvl[(size_t)M_TOT * N_TOT];   // qkv lo plane
__device__ float g_part[(size_t)8 * 128 * 4096];
__device__ __nv_bfloat16 g_ath[(size_t)128 * 4096];       // attn^T [bh][e][d] hi
__device__ __nv_bfloat16 g_atl[(size_t)128 * 4096];       // attn^T lo
__device__ __nv_bfloat16 g_xh[(size_t)M_TOT * K_TOT];
__device__ __nv_bfloat16 g_xl[(size_t)M_TOT * K_TOT];
__device__ __nv_bfloat16 g_wth[(size_t)N_TOT * K_TOT];
__device__ __nv_bfloat16 g_wtl[(size_t)N_TOT * K_TOT];

// ---------------------------------------------------------------------------
// helpers
// ---------------------------------------------------------------------------
__device__ __forceinline__ uint32_t smem_u32(const void* p) {
    uint32_t a;
    asm("{ .reg .u64 t; cvta.to.shared.u64 t, %1; cvt.u32.u64 %0, t; }" : "=r"(a) : "l"(p));
    return a;
}
__device__ __forceinline__ void cp16(uint32_t smem_dst, const void* gsrc) {
    asm volatile("cp.async.cg.shared.global [%0], [%1], 16;" :: "r"(smem_dst), "l"(gsrc));
}
__device__ __forceinline__ void cp_commit() {
    asm volatile("cp.async.commit_group;" ::: "memory");
}
__device__ __forceinline__ void ldsm4(uint32_t* r, uint32_t addr) {
    asm volatile("ldmatrix.sync.aligned.m8n8.x4.shared.b16 {%0,%1,%2,%3}, [%4];"
                 : "=r"(r[0]), "=r"(r[1]), "=r"(r[2]), "=r"(r[3]) : "r"(addr));
}
__device__ __forceinline__ void ldsm4t(uint32_t* r, uint32_t addr) {
    asm volatile("ldmatrix.sync.aligned.m8n8.x4.trans.shared.b16 {%0,%1,%2,%3}, [%4];"
                 : "=r"(r[0]), "=r"(r[1]), "=r"(r[2]), "=r"(r[3]) : "r"(addr));
}
__device__ __forceinline__ void mma16816(float* c, const uint32_t* a, const uint32_t* b) {
    asm volatile("mma.sync.aligned.m16n8k16.row.col.f32.bf16.bf16.f32 "
                 "{%0,%1,%2,%3}, {%4,%5,%6,%7}, {%8,%9}, {%0,%1,%2,%3};"
                 : "+f"(c[0]), "+f"(c[1]), "+f"(c[2]), "+f"(c[3])
                 : "r"(a[0]), "r"(a[1]), "r"(a[2]), "r"(a[3]), "r"(b[0]), "r"(b[1]));
}
__device__ __forceinline__ uint32_t pack_bf16(float x, float y) {
    __nv_bfloat162 t = __floats2bfloat162_rn(x, y);
    return *reinterpret_cast<uint32_t*>(&t);
}

// ---------------------------------------------------------------------------
// Conversion kernels (fp32 -> bf16 hi/lo split)
// ---------------------------------------------------------------------------
__global__ __launch_bounds__(256) void convert_x_kernel(const float* __restrict__ x)
{
    size_t i = ((size_t)blockIdx.x * 256 + threadIdx.x) * 8;
    float4 a = *(const float4*)(x + i);
    float4 b = *(const float4*)(x + i + 4);
    float v[8] = {a.x, a.y, a.z, a.w, b.x, b.y, b.z, b.w};
    __nv_bfloat16 hi[8], lo[8];
#pragma unroll
    for (int j = 0; j < 8; j++) {
        hi[j] = __float2bfloat16(v[j]);
        lo[j] = __float2bfloat16(v[j] - __bfloat162float(hi[j]));
    }
    *(uint4*)(g_xh + i) = *(uint4*)hi;
    *(uint4*)(g_xl + i) = *(uint4*)lo;
}

__global__ __launch_bounds__(256) void convert_w_kernel(const float* __restrict__ W)
{
    __shared__ float t[32][33];
    int x0 = blockIdx.x * 32;
    int y0 = blockIdx.y * 32;
    int tx = threadIdx.x, ty = threadIdx.y;
#pragma unroll
    for (int j = 0; j < 4; j++)
        t[ty + j * 8][tx] = W[(size_t)(y0 + ty + j * 8) * N_TOT + x0 + tx];
    __syncthreads();
#pragma unroll
    for (int j = 0; j < 4; j++) {
        int n = x0 + ty + j * 8;
        int k = y0 + tx;
        float v = t[tx][ty + j * 8];
        __nv_bfloat16 hi = __float2bfloat16(v);
        __nv_bfloat16 lo = __float2bfloat16(v - __bfloat162float(hi));
        g_wth[(size_t)n * K_TOT + k] = hi;
        g_wtl[(size_t)n * K_TOT + k] = lo;
    }
}

// ---------------------------------------------------------------------------
// K1: qkv = x @ W + b, mma.sync bf16 3-term split, SINGLE K pass.
// Block 256x128, BK=64, 16 k-chunks; per chunk load xh/xl/wh/wl planes and
// issue all 3 terms (hh, lh, hl) per fragment load. 512 threads, 16 warps,
// warp tile 32x64. 2 stages x 96KB. Epilogue staged via smem.
// ---------------------------------------------------------------------------
#define BM 256
#define BN 128
#define BK 64
#define NCHUNK 16
#define STAGE_BYTES 98304            // xh 32K | xl 32K | wh 16K | wl 16K
#define XH_OFF(s) ((s) * STAGE_BYTES)
#define XL_OFF(s) ((s) * STAGE_BYTES + 32768)
#define WH_OFF(s) ((s) * STAGE_BYTES + 65536)
#define WL_OFF(s) ((s) * STAGE_BYTES + 81920)
#define GEMM_SMEM (2 * STAGE_BYTES)  // 192 KB

__device__ __forceinline__ void load_chunk(uint32_t sb, int tid, int by, int bx, int c, int s)
{
    int koff = c * BK;
    const __nv_bfloat16* Ah = g_xh  + (size_t)(by * BM) * K_TOT + koff;
    const __nv_bfloat16* Al = g_xl  + (size_t)(by * BM) * K_TOT + koff;
    const __nv_bfloat16* Bh = g_wth + (size_t)(bx * BN) * K_TOT + koff;
    const __nv_bfloat16* Bl = g_wtl + (size_t)(bx * BN) * K_TOT + koff;
#pragma unroll
    for (int i = 0; i < 4; i++) {            // A planes: 2048 slots each
        int slot = i * 512 + tid;
        int r   = slot >> 3;
        int c16 = slot & 7;
        uint32_t off = (uint32_t)(r * 128 + ((c16 ^ (r & 7)) * 16));
        cp16(sb + XH_OFF(s) + off, Ah + (size_t)r * K_TOT + c16 * 8);
        cp16(sb + XL_OFF(s) + off, Al + (size_t)r * K_TOT + c16 * 8);
    }
#pragma unroll
    for (int i = 0; i < 2; i++) {            // B planes: 1024 slots each
        int slot = i * 512 + tid;
        int r   = slot >> 3;
        int c16 = slot & 7;
        uint32_t off = (uint32_t)(r * 128 + ((c16 ^ (r & 7)) * 16));
        cp16(sb + WH_OFF(s) + off, Bh + (size_t)r * K_TOT + c16 * 8);
        cp16(sb + WL_OFF(s) + off, Bl + (size_t)r * K_TOT + c16 * 8);
    }
}

__global__ __launch_bounds__(512, 1) void qkv_mma_kernel(const float* __restrict__ bias)
{
    extern __shared__ __align__(128) uint8_t smem[];
    uint32_t sb = smem_u32(smem);
    const int tid  = threadIdx.x;
    const int wid  = tid >> 5;
    const int lane = tid & 31;
    const int bx = blockIdx.x;    // N tile 0..23
    const int by = blockIdx.y;    // M tile 0..127
    const int wm = wid >> 1;      // 0..7  (32 M each)
    const int wn = wid & 1;       // 0..1  (64 N each)

    float acc[2][8][4];
#pragma unroll
    for (int mt = 0; mt < 2; mt++)
#pragma unroll
        for (int nt = 0; nt < 8; nt++)
#pragma unroll
            for (int j = 0; j < 4; j++) acc[mt][nt][j] = 0.f;

    load_chunk(sb, tid, by, bx, 0, 0);
    cp_commit();

    const int a_r = wm * 32 + (lane & 15);
    const int a_h = lane >> 4;
    const int b_r = wn * 64 + ((lane >> 4) << 3) + (lane & 7);
    const int b_h = (lane >> 3) & 1;

    for (int ch = 0; ch < NCHUNK; ch++) {
        __syncthreads();   // everyone done reading the stage we're about to fill
        if (ch + 1 < NCHUNK) load_chunk(sb, tid, by, bx, ch + 1, (ch + 1) & 1);
        cp_commit();
        asm volatile("cp.async.wait_group 1;" ::: "memory");
        __syncthreads();

        const int s = ch & 1;
        const uint32_t xh_b = sb + XH_OFF(s);
        const uint32_t xl_b = sb + XL_OFF(s);
        const uint32_t wh_b = sb + WH_OFF(s);
        const uint32_t wl_b = sb + WL_OFF(s);
#pragma unroll
        for (int ks = 0; ks < 4; ks++) {
            uint32_t ah[2][4], al[2][4];
#pragma unroll
            for (int mt = 0; mt < 2; mt++) {
                int r   = a_r + mt * 16;
                int c16 = ks * 2 + a_h;
                uint32_t off = (uint32_t)(r * 128 + ((c16 ^ (r & 7)) * 16));
                ldsm4(ah[mt], xh_b + off);
                ldsm4(al[mt], xl_b + off);
            }
#pragma unroll
            for (int np = 0; np < 4; np++) {
                int r   = b_r + np * 16;
                int c16 = ks * 2 + b_h;
                uint32_t off = (uint32_t)(r * 128 + ((c16 ^ (r & 7)) * 16));
                uint32_t qh[4], ql[4];
                ldsm4(qh, wh_b + off);
                ldsm4(ql, wl_b + off);
#pragma unroll
                for (int mt = 0; mt < 2; mt++) {
                    mma16816(acc[mt][np * 2 + 0], ah[mt], qh + 0);
                    mma16816(acc[mt][np * 2 + 1], ah[mt], qh + 2);
                    mma16816(acc[mt][np * 2 + 0], al[mt], qh + 0);
                    mma16816(acc[mt][np * 2 + 1], al[mt], qh + 2);
                    mma16816(acc[mt][np * 2 + 0], ah[mt], ql + 0);
                    mma16816(acc[mt][np * 2 + 1], ah[mt], ql + 2);
                }
            }
        }
    }
    asm volatile("cp.async.wait_group 0;" ::: "memory");
    __syncthreads();

    // ---- Epilogue via smem staging (coalesced 16B stores) ----
    const int ncol0 = bx * BN + wn * 64 + (lane & 3) * 2;
    float b0[8], b1[8];
#pragma unroll
    for (int nt = 0; nt < 8; nt++) {
        b0[nt] = __ldg(bias + ncol0 + nt * 8);
        b1[nt] = __ldg(bias + ncol0 + nt * 8 + 1);
    }
#pragma unroll
    for (int mt = 0; mt < 2; mt++)
#pragma unroll
        for (int half = 0; half < 2; half++) {
            int m = wm * 32 + mt * 16 + (lane >> 2) + half * 8;   // 0..255 (local)
#pragma unroll
            for (int nt = 0; nt < 8; nt++) {
                float vx = acc[mt][nt][half * 2 + 0] + b0[nt];
                float vy = acc[mt][nt][half * 2 + 1] + b1[nt];
                __nv_bfloat16 hx = __float2bfloat16(vx);
                __nv_bfloat16 hy = __float2bfloat16(vy);
                int chunk = wn * 8 + nt;                          // 0..15
                uint32_t off = (uint32_t)(m * 256 + (((chunk ^ (m & 7)) << 4))
                                          + (lane & 3) * 4);
                *(uint32_t*)(smem + off) = pack_bf16(vx, vy);
                *(uint32_t*)(smem + 65536 + off) =
                    pack_bf16(vx - __bfloat162float(hx), vy - __bfloat162float(hy));
            }
        }
    __syncthreads();

#pragma unroll
    for (int i = 0; i < 8; i++) {
        int slot = i * 512 + tid;           // 0..4095
        int r = slot >> 4;                  // 0..255
        int c = slot & 15;                  // 16B chunk
        uint32_t soff = (uint32_t)(r * 256 + ((c ^ (r & 7)) << 4));
        uint4 hv = *(uint4*)(smem + soff);
        uint4 lv = *(uint4*)(smem + 65536 + soff);
        size_t gbase = (size_t)(by * BM + r) * N_TOT + bx * BN + c * 8;
        *(uint4*)(g_qkvh + gbase) = hv;
        *(uint4*)(g_qkvl + gbase) = lv;
    }
}

// ---------------------------------------------------------------------------
// K2a: partial S over a 512-n chunk, tensor cores, bf16 planes via ldmatrix.trans.
// grid (8, 128). 256 threads. Subtile 64n, 2-stage cp.async (64KB smem).
// ---------------------------------------------------------------------------
#define K2_SMEM 65536

__device__ __forceinline__ void k2_load_sub(uint32_t sb, int tid,
                                            const __nv_bfloat16* qh, const __nv_bfloat16* ql,
                                            const __nv_bfloat16* kh, const __nv_bfloat16* kl,
                                            int n0, int stg)
{
    const __nv_bfloat16* src[4] = {qh, ql, kh, kl};
    uint32_t base = sb + stg * 32768;
#pragma unroll
    for (int p = 0; p < 4; p++) {
#pragma unroll
        for (int i = 0; i < 2; i++) {
            int slot = i * 256 + tid;
            int r   = slot >> 3;
            int c16 = slot & 7;
            uint32_t off = (uint32_t)(r * 128 + ((c16 ^ (r & 7)) << 4));
            cp16(base + p * 8192 + off, src[p] + (size_t)(n0 + r) * N_TOT + c16 * 8);
        }
    }
}

__global__ __launch_bounds__(256) void attn_part_kernel()
{
    extern __shared__ __align__(128) uint8_t smem[];
    uint32_t sb = smem_u32(smem);
    const int tid   = threadIdx.x;
    const int wid   = tid >> 5;
    const int lane  = tid & 31;
    const int chunk = blockIdx.x;
    const int bh    = blockIdx.y;
    const int b     = bh >> 4, h = bh & 15;

    const __nv_bfloat16* qh = g_qkvh + (size_t)b * SEQ * N_TOT + h * 64;
    const __nv_bfloat16* ql = g_qkvl + (size_t)b * SEQ * N_TOT + h * 64;
    const __nv_bfloat16* kh = qh + D_HID;
    const __nv_bfloat16* kl = ql + D_HID;

    const int wm = wid >> 2;
    const int wn = wid & 3;

    const int an = ((lane >> 4) & 1) * 8 + (lane & 7);
    const int ac = ((lane >> 3) & 1);
    const int bn = ((lane >> 3) & 1) * 8 + (lane & 7);
    const int bc = wn * 2 + (lane >> 4);

    float acc[2][2][4];
#pragma unroll
    for (int mt = 0; mt < 2; mt++)
#pragma unroll
        for (int nt = 0; nt < 2; nt++)
#pragma unroll
            for (int j = 0; j < 4; j++) acc[mt][nt][j] = 0.f;

    const int nbase = chunk * 512;
    k2_load_sub(sb, tid, qh, ql, kh, kl, nbase, 0);
    cp_commit();

    for (int t = 0; t < 8; t++) {
        __syncthreads();
        if (t + 1 < 8) k2_load_sub(sb, tid, qh, ql, kh, kl, nbase + (t + 1) * 64, (t + 1) & 1);
        cp_commit();
        asm volatile("cp.async.wait_group 1;" ::: "memory");
        __syncthreads();

        uint32_t stg = sb + (t & 1) * 32768;
#pragma unroll
        for (int ks = 0; ks < 4; ks++) {
            uint32_t aqh[2][4], aql[2][4];
#pragma unroll
            for (int mt = 0; mt < 2; mt++) {
                int n   = ks * 16 + an;
                int c16 = wm * 4 + mt * 2 + ac;
                uint32_t off = (uint32_t)(n * 128 + ((c16 ^ (n & 7)) << 4));
                ldsm4t(aqh[mt], stg + off);
                ldsm4t(aql[mt], stg + 8192 + off);
            }
            uint32_t bkh[2][2], bkl[2][2];
            {
                int n   = ks * 16 + bn;
                uint32_t off = (uint32_t)(n * 128 + ((bc ^ (n & 7)) << 4));
                uint32_t q[4];
                ldsm4t(q, stg + 16384 + off);
                bkh[0][0] = q[0]; bkh[0][1] = q[1]; bkh[1][0] = q[2]; bkh[1][1] = q[3];
                ldsm4t(q, stg + 24576 + off);
                bkl[0][0] = q[0]; bkl[0][1] = q[1]; bkl[1][0] = q[2]; bkl[1][1] = q[3];
            }
#pragma unroll
            for (int mt = 0; mt < 2; mt++)
#pragma unroll
                for (int nt = 0; nt < 2; nt++) {
                    mma16816(acc[mt][nt], aqh[mt], bkh[nt]);
                    mma16816(acc[mt][nt], aqh[mt], bkl[nt]);
                    mma16816(acc[mt][nt], aql[mt], bkh[nt]);
                }
        }
    }

    float* pg = g_part + ((size_t)chunk * 128 + bh) * 4096;
#pragma unroll
    for (int mt = 0; mt < 2; mt++)
#pragma unroll
        for (int nt = 0; nt < 2; nt++)
#pragma unroll
            for (int half = 0; half < 2; half++) {
                int d = wm * 32 + mt * 16 + (lane >> 2) + half * 8;
                int e = wn * 16 + nt * 8 + (lane & 3) * 2;
                float2 v;
                v.x = acc[mt][nt][half * 2 + 0];
                v.y = acc[mt][nt][half * 2 + 1];
                *(float2*)(pg + d * 64 + e) = v;
            }
}

// ---------------------------------------------------------------------------
// K2b: reduce 8 partials, scale, softmax over e; emit attn^T bf16 hi/lo.
// ---------------------------------------------------------------------------
__global__ __launch_bounds__(256) void attn_softmax_kernel()
{
    __shared__ float S[64 * 68 + 128];
    float* mrow = S + 64 * 68;
    float* irow = mrow + 64;

    const int tid = threadIdx.x;
    const int bh  = blockIdx.x;

#pragma unroll
    for (int i = 0; i < 16; i++) {
        int flat = i * 256 + tid;
        float v = 0.f;
#pragma unroll
        for (int c = 0; c < 8; c++)
            v += g_part[((size_t)c * 128 + bh) * 4096 + flat];
        int d = flat >> 6, e = flat & 63;
        S[d * 68 + e] = v * 0.125f;
    }
    __syncthreads();

    if (tid < 64) {
        float m = -3.4e38f;
#pragma unroll
        for (int e = 0; e < 64; e++) m = fmaxf(m, S[tid * 68 + e]);
        float sum = 0.f;
#pragma unroll
        for (int e = 0; e < 64; e++) sum += __expf(S[tid * 68 + e] - m);
        mrow[tid] = m;
        irow[tid] = 1.f / sum;
    }
    __syncthreads();

    __nv_bfloat16* ah = g_ath + (size_t)bh * 4096;
    __nv_bfloat16* al = g_atl + (size_t)bh * 4096;
#pragma unroll
    for (int i = 0; i < 16; i++) {
        int flat = i * 256 + tid;
        int e = flat >> 6, d = flat & 63;
        float a = __expf(S[d * 68 + e] - mrow[d]) * irow[d];
        __nv_bfloat16 hi = __float2bfloat16(a);
        ah[flat] = hi;
        al[flat] = __float2bfloat16(a - __bfloat162float(hi));
    }
}

// ---------------------------------------------------------------------------
// K3: out[n,e] = sum_d v[n,d] * attn[d,e] via tensor cores.
// ---------------------------------------------------------------------------
__global__ __launch_bounds__(256) void out_mma_kernel(float* __restrict__ out)
{
    __shared__ __align__(128) uint8_t smem[49152];
    uint32_t sb = smem_u32(smem);
    const int tid  = threadIdx.x;
    const int wid  = tid >> 5;
    const int lane = tid & 31;
    const int bh   = blockIdx.y;
    const int b    = bh >> 4, h = bh & 15;
    const int nt0  = blockIdx.x * 128;

    const __nv_bfloat16* agh = g_ath + (size_t)bh * 4096;
    const __nv_bfloat16* agl = g_atl + (size_t)bh * 4096;
#pragma unroll
    for (int i = 0; i < 2; i++) {
        int slot = i * 256 + tid;
        int r = slot >> 3, c = slot & 7;
        uint32_t dst = (uint32_t)(r * 128 + ((c ^ (r & 7)) << 4));
        cp16(sb + 32768 + dst, agh + r * 64 + c * 8);
        cp16(sb + 40960 + dst, agl + r * 64 + c * 8);
    }
    const __nv_bfloat16* vgh = g_qkvh + ((size_t)b * SEQ + nt0) * N_TOT + 2 * D_HID + h * 64;
    const __nv_bfloat16* vgl = g_qkvl + ((size_t)b * SEQ + nt0) * N_TOT + 2 * D_HID + h * 64;
#pragma unroll
    for (int i = 0; i < 4; i++) {
        int slot = i * 256 + tid;
        int r = slot >> 3, c = slot & 7;
        uint32_t off = (uint32_t)(r * 128 + ((c ^ (r & 7)) << 4));
        cp16(sb + off,         vgh + (size_t)r * N_TOT + c * 8);
        cp16(sb + 16384 + off, vgl + (size_t)r * N_TOT + c * 8);
    }
    cp_commit();
    asm volatile("cp.async.wait_group 0;" ::: "memory");
    __syncthreads();

    const int wm = wid >> 1;
    const int wn = wid & 1;
    const int a_r0 = wm * 32 + (lane & 15);
    const int a_h  = lane >> 4;
    const int b_r0 = wn * 32 + ((lane >> 4) << 3) + (lane & 7);
    const int b_h  = (lane >> 3) & 1;

    float acc[2][4][4];
#pragma unroll
    for (int mt = 0; mt < 2; mt++)
#pragma unroll
        for (int nt = 0; nt < 4; nt++)
#pragma unroll
            for (int j = 0; j < 4; j++) acc[mt][nt][j] = 0.f;

#pragma unroll
    for (int ks = 0; ks < 4; ks++) {
        uint32_t avh[2][4], avl[2][4];
#pragma unroll
        for (int mt = 0; mt < 2; mt++) {
            int r   = a_r0 + mt * 16;
            int c16 = ks * 2 + a_h;
            uint32_t so = (uint32_t)(r * 128 + ((c16 ^ (r & 7)) << 4));
            ldsm4(avh[mt], sb + so);
            ldsm4(avl[mt], sb + 16384 + so);
        }
        uint32_t bah[4][2], bal[4][2];
#pragma unroll
        for (int np = 0; np < 2; np++) {
            int r   = b_r0 + np * 16;
            int c16 = ks * 2 + b_h;
            uint32_t so = (uint32_t)(r * 128 + ((c16 ^ (r & 7)) << 4));
            uint32_t q[4];
            ldsm4(q, sb + 32768 + so);
            bah[np * 2 + 0][0] = q[0]; bah[np * 2 + 0][1] = q[1];
            bah[np * 2 + 1][0] = q[2]; bah[np * 2 + 1][1] = q[3];
            ldsm4(q, sb + 40960 + so);
            bal[np * 2 + 0][0] = q[0]; bal[np * 2 + 0][1] = q[1];
            bal[np * 2 + 1][0] = q[2]; bal[np * 2 + 1][1] = q[3];
        }
#pragma unroll
        for (int mt = 0; mt < 2; mt++)
#pragma unroll
            for (int nt = 0; nt < 4; nt++) {
                mma16816(acc[mt][nt], avh[mt], bah[nt]);
                mma16816(acc[mt][nt], avh[mt], bal[nt]);
                mma16816(acc[mt][nt], avl[mt], bah[nt]);
            }
    }

#pragma unroll
    for (int mt = 0; mt < 2; mt++)
#pragma unroll
        for (int half = 0; half < 2; half++) {
            int n = nt0 + wm * 32 + mt * 16 + (lane >> 2) + half * 8;
            float* orow = out + ((size_t)b * SEQ + n) * D_HID + h * 64
                          + wn * 32 + (lane & 3) * 2;
#pragma unroll
            for (int nt = 0; nt < 4; nt++) {
                float2 v;
                v.x = acc[mt][nt][half * 2 + 0];
                v.y = acc[mt][nt][half * 2 + 1];
                *(float2*)(orow + nt * 8) = v;
            }
        }
}

// ---------------------------------------------------------------------------
extern "C" void kernel_launch(void* const* d_in, const int* in_sizes, int n_in,
                              void* d_out, int out_size)
{
    const float* x    = (const float*)d_in[0];
    const float* W    = (const float*)d_in[1];
    const float* bias = (const float*)d_in[2];
    float* out = (float*)d_out;

    convert_x_kernel<<<(M_TOT * K_TOT) / (256 * 8), 256>>>(x);
    convert_w_kernel<<<dim3(N_TOT / 32, K_TOT / 32), dim3(32, 8)>>>(W);

    cudaFuncSetAttribute(qkv_mma_kernel, cudaFuncAttributeMaxDynamicSharedMemorySize, GEMM_SMEM);
    qkv_mma_kernel<<<dim3(N_TOT / BN, M_TOT / BM), 512, GEMM_SMEM>>>(bias);

    cudaFuncSetAttribute(attn_part_kernel, cudaFuncAttributeMaxDynamicSharedMemorySize, K2_SMEM);
    attn_part_kernel<<<dim3(8, BATCH * N_HEADS), 256, K2_SMEM>>>();

    attn_softmax_kernel<<<BATCH * N_HEADS, 256>>>();

    out_mma_kernel<<<dim3(SEQ / 128, BATCH * N_HEADS), 256>>>(out);
}